// round 5
// baseline (speedup 1.0000x reference)
#include <cuda_runtime.h>
#include <cstdint>

#define B_  2
#define S_  2048
#define D_  1024
#define H_  16
#define HD_ 64
#define M_  (B_*S_)   // 4096

// ---------------------------------------------------------------------------
// Scratch (allocation-free rule: __device__ globals)
// ---------------------------------------------------------------------------
__device__ float g_q[B_*H_*S_*HD_];   // [b,h,s,hd]  tf32-rounded, Q pre-scaled
__device__ float g_k[B_*H_*S_*HD_];
__device__ float g_v[B_*H_*S_*HD_];
__device__ float g_ao[M_*D_];         // attention out (tf32-rounded)
__device__ float g_wt[4*D_*D_];       // transposed weights [n][k], tf32-rounded
__device__ float g_xr[M_*D_];         // x, tf32-rounded

// ---------------------------------------------------------------------------
__device__ __forceinline__ float to_tf32(float x) {
    uint32_t u;
    asm("cvt.rna.tf32.f32 %0, %1;" : "=r"(u) : "f"(x));
    return __uint_as_float(u);
}
__device__ __forceinline__ uint32_t smem_u32(const void* p) {
    uint32_t a;
    asm("{ .reg .u64 t; cvta.to.shared.u64 t, %1; cvt.u32.u64 %0, t; }" : "=r"(a) : "l"(p));
    return a;
}
__device__ __forceinline__ void cp16(void* smem_dst, const void* gmem_src) {
    asm volatile("cp.async.cg.shared.global [%0], [%1], 16;"
                 :: "r"(smem_u32(smem_dst)), "l"(gmem_src));
}
#define CP_COMMIT() asm volatile("cp.async.commit_group;" ::: "memory")
#define CP_WAIT0()  asm volatile("cp.async.wait_group 0;" ::: "memory")
#define CP_WAIT1()  asm volatile("cp.async.wait_group 1;" ::: "memory")

__device__ __forceinline__ void mma_tf32(float* d, const uint32_t* a, const uint32_t* b) {
    asm volatile(
        "mma.sync.aligned.m16n8k8.row.col.f32.tf32.tf32.f32 "
        "{%0,%1,%2,%3}, {%4,%5,%6,%7}, {%8,%9}, {%0,%1,%2,%3};"
        : "+f"(d[0]), "+f"(d[1]), "+f"(d[2]), "+f"(d[3])
        : "r"(a[0]), "r"(a[1]), "r"(a[2]), "r"(a[3]), "r"(b[0]), "r"(b[1]));
}

// ---------------------------------------------------------------------------
// x pre-round (elementwise, RNA -> tf32-representable fp32)
// ---------------------------------------------------------------------------
__global__ __launch_bounds__(256)
void round_x_kernel(const float* __restrict__ x)
{
    size_t i = ((size_t)blockIdx.x * 256 + threadIdx.x) * 4;
    const size_t stride = (size_t)gridDim.x * 256 * 4;
    for (; i < (size_t)M_ * D_; i += stride) {
        float4 v = *(const float4*)&x[i];
        v.x = to_tf32(v.x); v.y = to_tf32(v.y);
        v.z = to_tf32(v.z); v.w = to_tf32(v.w);
        *(float4*)&g_xr[i] = v;
    }
}

// ---------------------------------------------------------------------------
// Weight transpose + tf32 round: dst[n][k] = tf32(src[k][n])
// ---------------------------------------------------------------------------
__global__ __launch_bounds__(256)
void transpose_kernel(const float* __restrict__ src, int widx)
{
    __shared__ float t[32][33];
    float* dst = g_wt + (size_t)widx * D_ * D_;
    int bx = blockIdx.x * 32, by = blockIdx.y * 32;
    int tx = threadIdx.x, ty = threadIdx.y;
    #pragma unroll
    for (int i = 0; i < 32; i += 8)
        t[ty + i][tx] = src[(size_t)(by + ty + i) * D_ + bx + tx];
    __syncthreads();
    #pragma unroll
    for (int i = 0; i < 32; i += 8)
        dst[(size_t)(bx + ty + i) * D_ + by + tx] = to_tf32(t[tx][ty + i]);
}

// ---------------------------------------------------------------------------
// Pipelined tf32 GEMM core: C = A . Wt^T (+bias). cp.async double-buffered.
// CTA 128x128, 256 thr, 8 warps (2x4), K chunks of 32.
// smem: dynamic, As[2]/Bs[2] each [128][36] floats.
// ---------------------------------------------------------------------------
#define GP 36
#define GBUF (128 * GP)                 // floats per buffer
#define GEMM_SMEM (4 * GBUF * 4)        // 73728 B

// QKV fused: blockIdx.z = 0/1/2 -> Q/K/V
__global__ __launch_bounds__(256, 2)
void gemm_qkv_kernel(const float* __restrict__ bq,
                     const float* __restrict__ bk,
                     const float* __restrict__ bv)
{
    extern __shared__ float smf[];
    float* As[2] = { smf,            smf + GBUF };
    float* Bs[2] = { smf + 2*GBUF,   smf + 3*GBUF };

    const int tid = threadIdx.x;
    const int wid = tid >> 5, lid = tid & 31;
    const int g = lid >> 2, tig = lid & 3;
    const int wm = (wid >> 2) * 64;
    const int wn = (wid & 3) * 32;
    const int bm = blockIdx.y * 128;
    const int bn = blockIdx.x * 128;
    const int z  = blockIdx.z;

    const float* A  = g_xr;
    const float* Bt = g_wt + (size_t)z * D_ * D_;
    const float* bias = (z == 0) ? bq : (z == 1) ? bk : bv;
    float* dst = (z == 0) ? g_q : (z == 1) ? g_k : g_v;
    const float scale = (z == 0) ? 0.125f : 1.0f;

    const int lrow = tid >> 3, lv = (tid & 7) * 4;   // per-thread base (4 rows apart)

    float acc[4][4][4];
    #pragma unroll
    for (int mb = 0; mb < 4; mb++)
        #pragma unroll
        for (int nb = 0; nb < 4; nb++)
            #pragma unroll
            for (int i = 0; i < 4; i++) acc[mb][nb][i] = 0.f;

    // pipeline prologue
    {
        #pragma unroll
        for (int i = 0; i < 4; i++) {
            int row = lrow + i * 32;
            cp16(&As[0][row * GP + lv], &A [(size_t)(bm + row) * D_ + lv]);
            cp16(&Bs[0][row * GP + lv], &Bt[(size_t)(bn + row) * D_ + lv]);
        }
        CP_COMMIT();
    }

    for (int c = 0; c < D_ / 32; c++) {
        const int cur = c & 1;
        if (c + 1 < D_ / 32) {
            const int k0 = (c + 1) * 32, nxt = cur ^ 1;
            #pragma unroll
            for (int i = 0; i < 4; i++) {
                int row = lrow + i * 32;
                cp16(&As[nxt][row * GP + lv], &A [(size_t)(bm + row) * D_ + k0 + lv]);
                cp16(&Bs[nxt][row * GP + lv], &Bt[(size_t)(bn + row) * D_ + k0 + lv]);
            }
            CP_COMMIT();
            CP_WAIT1();
        } else {
            CP_WAIT0();
        }
        __syncthreads();

        const float* Ab = As[cur];
        const float* Bb = Bs[cur];
        #pragma unroll
        for (int ks = 0; ks < 4; ks++) {
            const int k = ks * 8;
            uint32_t af[4][4], bf[4][2];
            #pragma unroll
            for (int mb = 0; mb < 4; mb++) {
                int m = wm + mb * 16 + g;
                af[mb][0] = __float_as_uint(Ab[(m    ) * GP + k + tig]);
                af[mb][1] = __float_as_uint(Ab[(m + 8) * GP + k + tig]);
                af[mb][2] = __float_as_uint(Ab[(m    ) * GP + k + tig + 4]);
                af[mb][3] = __float_as_uint(Ab[(m + 8) * GP + k + tig + 4]);
            }
            #pragma unroll
            for (int nb = 0; nb < 4; nb++) {
                int n = wn + nb * 8 + g;
                bf[nb][0] = __float_as_uint(Bb[n * GP + k + tig]);
                bf[nb][1] = __float_as_uint(Bb[n * GP + k + tig + 4]);
            }
            #pragma unroll
            for (int mb = 0; mb < 4; mb++)
                #pragma unroll
                for (int nb = 0; nb < 4; nb++)
                    mma_tf32(acc[mb][nb], af[mb], bf[nb]);
        }
        __syncthreads();
    }

    // epilogue: round to tf32 (Q pre-scaled), scatter to [b,h,s,hd]
    #pragma unroll
    for (int mb = 0; mb < 4; mb++) {
        #pragma unroll
        for (int half = 0; half < 2; half++) {
            const int m = bm + wm + mb * 16 + g + half * 8;
            const int b = m >> 11, s = m & 2047;
            #pragma unroll
            for (int nb = 0; nb < 4; nb++) {
                const int n = bn + wn + nb * 8 + 2 * tig;
                const int h = n >> 6, hd = n & 63;
                float2 o;
                o.x = to_tf32((acc[mb][nb][half * 2 + 0] + __ldg(&bias[n]))     * scale);
                o.y = to_tf32((acc[mb][nb][half * 2 + 1] + __ldg(&bias[n + 1])) * scale);
                *(float2*)&dst[(((size_t)(b * H_ + h)) * S_ + s) * HD_ + hd] = o;
            }
        }
    }
}

// O-projection: A = g_ao (already tf32), out = final fp32
__global__ __launch_bounds__(256, 2)
void gemm_o_kernel(const float* __restrict__ bias, float* __restrict__ outp)
{
    extern __shared__ float smf[];
    float* As[2] = { smf,            smf + GBUF };
    float* Bs[2] = { smf + 2*GBUF,   smf + 3*GBUF };

    const int tid = threadIdx.x;
    const int wid = tid >> 5, lid = tid & 31;
    const int g = lid >> 2, tig = lid & 3;
    const int wm = (wid >> 2) * 64;
    const int wn = (wid & 3) * 32;
    const int bm = blockIdx.y * 128;
    const int bn = blockIdx.x * 128;

    const float* A  = g_ao;
    const float* Bt = g_wt + (size_t)3 * D_ * D_;
    const int lrow = tid >> 3, lv = (tid & 7) * 4;

    float acc[4][4][4];
    #pragma unroll
    for (int mb = 0; mb < 4; mb++)
        #pragma unroll
        for (int nb = 0; nb < 4; nb++)
            #pragma unroll
            for (int i = 0; i < 4; i++) acc[mb][nb][i] = 0.f;

    {
        #pragma unroll
        for (int i = 0; i < 4; i++) {
            int row = lrow + i * 32;
            cp16(&As[0][row * GP + lv], &A [(size_t)(bm + row) * D_ + lv]);
            cp16(&Bs[0][row * GP + lv], &Bt[(size_t)(bn + row) * D_ + lv]);
        }
        CP_COMMIT();
    }

    for (int c = 0; c < D_ / 32; c++) {
        const int cur = c & 1;
        if (c + 1 < D_ / 32) {
            const int k0 = (c + 1) * 32, nxt = cur ^ 1;
            #pragma unroll
            for (int i = 0; i < 4; i++) {
                int row = lrow + i * 32;
                cp16(&As[nxt][row * GP + lv], &A [(size_t)(bm + row) * D_ + k0 + lv]);
                cp16(&Bs[nxt][row * GP + lv], &Bt[(size_t)(bn + row) * D_ + k0 + lv]);
            }
            CP_COMMIT();
            CP_WAIT1();
        } else {
            CP_WAIT0();
        }
        __syncthreads();

        const float* Ab = As[cur];
        const float* Bb = Bs[cur];
        #pragma unroll
        for (int ks = 0; ks < 4; ks++) {
            const int k = ks * 8;
            uint32_t af[4][4], bf[4][2];
            #pragma unroll
            for (int mb = 0; mb < 4; mb++) {
                int m = wm + mb * 16 + g;
                af[mb][0] = __float_as_uint(Ab[(m    ) * GP + k + tig]);
                af[mb][1] = __float_as_uint(Ab[(m + 8) * GP + k + tig]);
                af[mb][2] = __float_as_uint(Ab[(m    ) * GP + k + tig + 4]);
                af[mb][3] = __float_as_uint(Ab[(m + 8) * GP + k + tig + 4]);
            }
            #pragma unroll
            for (int nb = 0; nb < 4; nb++) {
                int n = wn + nb * 8 + g;
                bf[nb][0] = __float_as_uint(Bb[n * GP + k + tig]);
                bf[nb][1] = __float_as_uint(Bb[n * GP + k + tig + 4]);
            }
            #pragma unroll
            for (int mb = 0; mb < 4; mb++)
                #pragma unroll
                for (int nb = 0; nb < 4; nb++)
                    mma_tf32(acc[mb][nb], af[mb], bf[nb]);
        }
        __syncthreads();
    }

    #pragma unroll
    for (int mb = 0; mb < 4; mb++) {
        #pragma unroll
        for (int half = 0; half < 2; half++) {
            const int m = bm + wm + mb * 16 + g + half * 8;
            #pragma unroll
            for (int nb = 0; nb < 4; nb++) {
                const int n = bn + wn + nb * 8 + 2 * tig;
                float2 o;
                o.x = acc[mb][nb][half * 2 + 0] + __ldg(&bias[n]);
                o.y = acc[mb][nb][half * 2 + 1] + __ldg(&bias[n + 1]);
                *(float2*)&outp[(size_t)m * D_ + n] = o;
            }
        }
    }
}

// ---------------------------------------------------------------------------
// Flash attention, tf32 mma. Inputs pre-rounded (Q pre-scaled).
// K/V software-pipelined through registers; Q via cp.async.
// ---------------------------------------------------------------------------
#define AP 68
#define ATT_SMEM (384 * AP * 4)

__global__ __launch_bounds__(256, 2)
void attn_mma_kernel()
{
    extern __shared__ float sm[];
    float* Qs = sm;                 // [128][AP]
    float* Ks = sm + 128 * AP;      // [64][AP]
    float* Vt = sm + 192 * AP;      // [64][AP]  (hd x kv)
    float* Ps = sm + 256 * AP;      // [128][AP]

    const int tid = threadIdx.x;
    const int wid = tid >> 5, lid = tid & 31;
    const int g = lid >> 2, tig = lid & 3;
    const int wq = wid * 16;
    const int bh = blockIdx.y;
    const int q0 = blockIdx.x * 128;

    const float* Qb = g_q + (size_t)bh * S_ * HD_;
    const float* Kb = g_k + (size_t)bh * S_ * HD_;
    const float* Vb = g_v + (size_t)bh * S_ * HD_;

    // Q tile via cp.async (raw: pre-scaled + pre-rounded)
    #pragma unroll
    for (int i = 0; i < 8; i++) {
        int idx = tid + i * 256;
        int r = idx >> 4, c4 = (idx & 15) * 4;
        cp16(&Qs[r * AP + c4], &Qb[(size_t)(q0 + r) * HD_ + c4]);
    }
    CP_COMMIT();

    // K/V register prefetch (tile 0)
    float4 kreg[4], vreg[4];
    #pragma unroll
    for (int i = 0; i < 4; i++) {
        int idx = tid + i * 256;
        int kr = idx >> 4, kc = (idx & 15) * 4;
        kreg[i] = *(const float4*)&Kb[(size_t)kr * HD_ + kc];
        int vr = (idx >> 1) & 63;
        int vc = ((idx & 1) | ((idx >> 7) << 1)) * 4;
        vreg[i] = *(const float4*)&Vb[(size_t)vr * HD_ + vc];
    }

    float m_i[2] = {-1e30f, -1e30f}, l_i[2] = {0.f, 0.f};
    float acc[8][4];
    #pragma unroll
    for (int nb = 0; nb < 8; nb++)
        #pragma unroll
        for (int i = 0; i < 4; i++) acc[nb][i] = 0.f;

    for (int t = 0; t < S_; t += 64) {
        __syncthreads();   // previous tile's Ks/Vt reads complete
        // store prefetched K (natural) and V (transposed)
        #pragma unroll
        for (int i = 0; i < 4; i++) {
            int idx = tid + i * 256;
            int kr = idx >> 4, kc = (idx & 15) * 4;
            *(float4*)&Ks[kr * AP + kc] = kreg[i];
            int vr = (idx >> 1) & 63;
            int vc = ((idx & 1) | ((idx >> 7) << 1)) * 4;
            Vt[(vc + 0) * AP + vr] = vreg[i].x;
            Vt[(vc + 1) * AP + vr] = vreg[i].y;
            Vt[(vc + 2) * AP + vr] = vreg[i].z;
            Vt[(vc + 3) * AP + vr] = vreg[i].w;
        }
        // issue next tile's loads (hide behind this tile's compute)
        if (t + 64 < S_) {
            #pragma unroll
            for (int i = 0; i < 4; i++) {
                int idx = tid + i * 256;
                int kr = idx >> 4, kc = (idx & 15) * 4;
                kreg[i] = *(const float4*)&Kb[(size_t)(t + 64 + kr) * HD_ + kc];
                int vr = (idx >> 1) & 63;
                int vc = ((idx & 1) | ((idx >> 7) << 1)) * 4;
                vreg[i] = *(const float4*)&Vb[(size_t)(t + 64 + vr) * HD_ + vc];
            }
        }
        if (t == 0) CP_WAIT0();   // Q arrived
        __syncthreads();

        // S = Q K^T
        float s[8][4];
        #pragma unroll
        for (int nb = 0; nb < 8; nb++)
            #pragma unroll
            for (int i = 0; i < 4; i++) s[nb][i] = 0.f;

        #pragma unroll
        for (int kk = 0; kk < 64; kk += 8) {
            uint32_t af[4];
            af[0] = __float_as_uint(Qs[(wq + g    ) * AP + kk + tig]);
            af[1] = __float_as_uint(Qs[(wq + g + 8) * AP + kk + tig]);
            af[2] = __float_as_uint(Qs[(wq + g    ) * AP + kk + tig + 4]);
            af[3] = __float_as_uint(Qs[(wq + g + 8) * AP + kk + tig + 4]);
            #pragma unroll
            for (int nb = 0; nb < 8; nb++) {
                uint32_t bf[2];
                bf[0] = __float_as_uint(Ks[(nb * 8 + g) * AP + kk + tig]);
                bf[1] = __float_as_uint(Ks[(nb * 8 + g) * AP + kk + tig + 4]);
                mma_tf32(s[nb], af, bf);
            }
        }

        // online softmax (warp-local rows wq+g, wq+g+8)
        float mx[2] = {-1e30f, -1e30f};
        #pragma unroll
        for (int nb = 0; nb < 8; nb++) {
            mx[0] = fmaxf(mx[0], fmaxf(s[nb][0], s[nb][1]));
            mx[1] = fmaxf(mx[1], fmaxf(s[nb][2], s[nb][3]));
        }
        #pragma unroll
        for (int h = 0; h < 2; h++) {
            mx[h] = fmaxf(mx[h], __shfl_xor_sync(0xffffffffu, mx[h], 1));
            mx[h] = fmaxf(mx[h], __shfl_xor_sync(0xffffffffu, mx[h], 2));
        }
        float mnew[2], al[2], rs[2] = {0.f, 0.f};
        #pragma unroll
        for (int h = 0; h < 2; h++) {
            mnew[h] = fmaxf(m_i[h], mx[h]);
            al[h] = __expf(m_i[h] - mnew[h]);
            m_i[h] = mnew[h];
        }
        #pragma unroll
        for (int nb = 0; nb < 8; nb++) {
            s[nb][0] = __expf(s[nb][0] - mnew[0]);
            s[nb][1] = __expf(s[nb][1] - mnew[0]);
            s[nb][2] = __expf(s[nb][2] - mnew[1]);
            s[nb][3] = __expf(s[nb][3] - mnew[1]);
            rs[0] += s[nb][0] + s[nb][1];
            rs[1] += s[nb][2] + s[nb][3];
        }
        #pragma unroll
        for (int h = 0; h < 2; h++) {
            rs[h] += __shfl_xor_sync(0xffffffffu, rs[h], 1);
            rs[h] += __shfl_xor_sync(0xffffffffu, rs[h], 2);
            l_i[h] = l_i[h] * al[h] + rs[h];
        }
        #pragma unroll
        for (int nb = 0; nb < 8; nb++) {
            acc[nb][0] *= al[0]; acc[nb][1] *= al[0];
            acc[nb][2] *= al[1]; acc[nb][3] *= al[1];
        }

        // P -> warp-private smem (tf32)
        #pragma unroll
        for (int nb = 0; nb < 8; nb++) {
            float2 p0 = make_float2(to_tf32(s[nb][0]), to_tf32(s[nb][1]));
            float2 p1 = make_float2(to_tf32(s[nb][2]), to_tf32(s[nb][3]));
            *(float2*)&Ps[(wq + g    ) * AP + nb * 8 + 2 * tig] = p0;
            *(float2*)&Ps[(wq + g + 8) * AP + nb * 8 + 2 * tig] = p1;
        }
        __syncwarp();

        // O += P V
        #pragma unroll
        for (int kk = 0; kk < 64; kk += 8) {
            uint32_t af[4];
            af[0] = __float_as_uint(Ps[(wq + g    ) * AP + kk + tig]);
            af[1] = __float_as_uint(Ps[(wq + g + 8) * AP + kk + tig]);
            af[2] = __float_as_uint(Ps[(wq + g    ) * AP + kk + tig + 4]);
            af[3] = __float_as_uint(Ps[(wq + g + 8) * AP + kk + tig + 4]);
            #pragma unroll
            for (int nb = 0; nb < 8; nb++) {
                uint32_t bf[2];
                bf[0] = __float_as_uint(Vt[(nb * 8 + g) * AP + kk + tig]);
                bf[1] = __float_as_uint(Vt[(nb * 8 + g) * AP + kk + tig + 4]);
                mma_tf32(acc[nb], af, bf);
            }
        }
        __syncwarp();
    }

    // epilogue: normalize, tf32-round (for O-proj cp.async), write g_ao
    const int bb = bh / H_, h = bh % H_;
    const float inv0 = 1.0f / l_i[0], inv1 = 1.0f / l_i[1];
    const int s0 = q0 + wq + g;
    #pragma unroll
    for (int nb = 0; nb < 8; nb++) {
        const int col = h * HD_ + nb * 8 + 2 * tig;
        float2 o0 = make_float2(to_tf32(acc[nb][0] * inv0), to_tf32(acc[nb][1] * inv0));
        float2 o1 = make_float2(to_tf32(acc[nb][2] * inv1), to_tf32(acc[nb][3] * inv1));
        *(float2*)&g_ao[(size_t)(bb * S_ + s0    ) * D_ + col] = o0;
        *(float2*)&g_ao[(size_t)(bb * S_ + s0 + 8) * D_ + col] = o1;
    }
}

// ---------------------------------------------------------------------------
extern "C" void kernel_launch(void* const* d_in, const int* in_sizes, int n_in,
                              void* d_out, int out_size)
{
    const float* x  = (const float*)d_in[0];
    const float* Wq = (const float*)d_in[1];
    const float* bq = (const float*)d_in[2];
    const float* Wk = (const float*)d_in[3];
    const float* bk = (const float*)d_in[4];
    const float* Wv = (const float*)d_in[5];
    const float* bv = (const float*)d_in[6];
    const float* Wo = (const float*)d_in[7];
    const float* bo = (const float*)d_in[8];
    float* out = (float*)d_out;

    static bool attr_done = false;
    if (!attr_done) {
        cudaFuncSetAttribute(attn_mma_kernel,
                             cudaFuncAttributeMaxDynamicSharedMemorySize, ATT_SMEM);
        cudaFuncSetAttribute(gemm_qkv_kernel,
                             cudaFuncAttributeMaxDynamicSharedMemorySize, GEMM_SMEM);
        cudaFuncSetAttribute(gemm_o_kernel,
                             cudaFuncAttributeMaxDynamicSharedMemorySize, GEMM_SMEM);
        attr_done = true;
    }

    round_x_kernel<<<1024, 256>>>(x);
    dim3 gT(D_ / 32, D_ / 32);
    transpose_kernel<<<gT, dim3(32, 8)>>>(Wq, 0);
    transpose_kernel<<<gT, dim3(32, 8)>>>(Wk, 1);
    transpose_kernel<<<gT, dim3(32, 8)>>>(Wv, 2);
    transpose_kernel<<<gT, dim3(32, 8)>>>(Wo, 3);

    dim3 gQKV(D_ / 128, M_ / 128, 3);   // (8, 32, 3)
    gemm_qkv_kernel<<<gQKV, 256, GEMM_SMEM>>>(bq, bk, bv);

    dim3 gAttn(S_ / 128, B_ * H_);      // (16, 32)
    attn_mma_kernel<<<gAttn, 256, ATT_SMEM>>>();

    dim3 gO(D_ / 128, M_ / 128);        // (8, 32)
    gemm_o_kernel<<<gO, 256, GEMM_SMEM>>>(bo, out);
}

// round 6
// speedup vs baseline: 1.0062x; 1.0062x over previous
#include <cuda_runtime.h>
#include <cstdint>

#define B_  2
#define S_  2048
#define D_  1024
#define H_  16
#define HD_ 64
#define M_  (B_*S_)   // 4096

// ---------------------------------------------------------------------------
// Scratch (allocation-free rule: __device__ globals)
// ---------------------------------------------------------------------------
__device__ float g_q[B_*H_*S_*HD_];   // [b,h,s,hd]
__device__ float g_k[B_*H_*S_*HD_];
__device__ float g_v[B_*H_*S_*HD_];
__device__ float g_ao[M_*D_];         // attention out, [b,s, h*hd]

// ---------------------------------------------------------------------------
__device__ __forceinline__ float to_tf32(float x) {
    uint32_t u;
    asm("cvt.rna.tf32.f32 %0, %1;" : "=r"(u) : "f"(x));
    return __uint_as_float(u);
}

__device__ __forceinline__ void mma_tf32(float* d, const uint32_t* a, const uint32_t* b) {
    asm volatile(
        "mma.sync.aligned.m16n8k8.row.col.f32.tf32.tf32.f32 "
        "{%0,%1,%2,%3}, {%4,%5,%6,%7}, {%8,%9}, {%0,%1,%2,%3};"
        : "+f"(d[0]), "+f"(d[1]), "+f"(d[2]), "+f"(d[3])
        : "r"(a[0]), "r"(a[1]), "r"(a[2]), "r"(a[3]), "r"(b[0]), "r"(b[1]));
}

// ---------------------------------------------------------------------------
// tf32 mma.sync GEMM: C[m][n] = A[m][:] . W[:][n] + bias[n]
// W consumed in natural [k][n] layout; the B smem tile is transposed during
// the fill (register transpose, conflict-free scalar stores).
// MODE 0: A=g_ao, out=outp row-major [M,D]
// MODE 1/2/3: A=x, out=g_q/g_k/g_v scattered to [b,h,s,hd]
// CTA 128x128, 256 thr, 8 warps (2x4), warp tile 64x32, K chunks of 32.
// ---------------------------------------------------------------------------
template<int MODE>
__global__ __launch_bounds__(256)
void gemm_mma_kernel(const float* __restrict__ Ap,
                     const float* __restrict__ W,
                     const float* __restrict__ bias,
                     float* __restrict__ outp)
{
    __shared__ float As[128][36];   // [m][k]
    __shared__ float Bs[128][36];   // [n][k]  (transposed W tile)

    const int tid = threadIdx.x;
    const int wid = tid >> 5, lid = tid & 31;
    const int g = lid >> 2, tig = lid & 3;
    const int wm = (wid >> 2) * 64;
    const int wn = (wid & 3) * 32;
    const int bm = blockIdx.y * 128;
    const int bn = blockIdx.x * 128;

    const float* A = (MODE == 0) ? (const float*)g_ao : Ap;

    float acc[4][4][4];
    #pragma unroll
    for (int mb = 0; mb < 4; mb++)
        #pragma unroll
        for (int nb = 0; nb < 4; nb++)
            #pragma unroll
            for (int i = 0; i < 4; i++) acc[mb][nb][i] = 0.f;

    for (int c = 0; c < D_ / 32; c++) {
        const int k0 = c * 32;
        // A tile: 128 rows x 32 cols, natural layout, coalesced float4
        #pragma unroll
        for (int i = 0; i < 4; i++) {
            int idx = tid + i * 256;
            int row = idx >> 3, v = (idx & 7) * 4;
            float4 av = *(const float4*)&A[(size_t)(bm + row) * D_ + k0 + v];
            av.x = to_tf32(av.x); av.y = to_tf32(av.y);
            av.z = to_tf32(av.z); av.w = to_tf32(av.w);
            *(float4*)&As[row][v] = av;
        }
        // B tile: W[k0:k0+32][bn:bn+128] -> Bs[n][k] transposed.
        // idx bits: c4 = bit0 | bits6-9 (col group 0..31), r = bits1-5 (k row).
        // Store bank = (c4*16 + j*4 + r) mod 32: within-warp c4 in {0,1},
        // r in 0..15 -> 32 distinct banks per store phase (conflict-free).
        #pragma unroll
        for (int i = 0; i < 4; i++) {
            int idx = tid + i * 256;
            int r  = (idx >> 1) & 31;
            int c4 = (idx & 1) | (((idx >> 6) & 15) << 1);
            float4 wv = *(const float4*)&W[(size_t)(k0 + r) * D_ + bn + c4 * 4];
            Bs[c4 * 4 + 0][r] = to_tf32(wv.x);
            Bs[c4 * 4 + 1][r] = to_tf32(wv.y);
            Bs[c4 * 4 + 2][r] = to_tf32(wv.z);
            Bs[c4 * 4 + 3][r] = to_tf32(wv.w);
        }
        __syncthreads();

        #pragma unroll
        for (int ks = 0; ks < 4; ks++) {
            const int k = ks * 8;
            uint32_t af[4][4], bf[4][2];
            #pragma unroll
            for (int mb = 0; mb < 4; mb++) {
                int m = wm + mb * 16 + g;
                af[mb][0] = __float_as_uint(As[m    ][k + tig]);
                af[mb][1] = __float_as_uint(As[m + 8][k + tig]);
                af[mb][2] = __float_as_uint(As[m    ][k + tig + 4]);
                af[mb][3] = __float_as_uint(As[m + 8][k + tig + 4]);
            }
            #pragma unroll
            for (int nb = 0; nb < 4; nb++) {
                int n = wn + nb * 8 + g;
                bf[nb][0] = __float_as_uint(Bs[n][k + tig]);
                bf[nb][1] = __float_as_uint(Bs[n][k + tig + 4]);
            }
            #pragma unroll
            for (int mb = 0; mb < 4; mb++)
                #pragma unroll
                for (int nb = 0; nb < 4; nb++)
                    mma_tf32(acc[mb][nb], af[mb], bf[nb]);
        }
        __syncthreads();
    }

    float* qkv = (MODE == 1) ? g_q : (MODE == 2) ? g_k : g_v;
    #pragma unroll
    for (int mb = 0; mb < 4; mb++) {
        #pragma unroll
        for (int half = 0; half < 2; half++) {
            const int m = bm + wm + mb * 16 + g + half * 8;
            #pragma unroll
            for (int nb = 0; nb < 4; nb++) {
                const int n = bn + wn + nb * 8 + 2 * tig;
                float2 o;
                o.x = acc[mb][nb][half * 2 + 0] + __ldg(&bias[n]);
                o.y = acc[mb][nb][half * 2 + 1] + __ldg(&bias[n + 1]);
                if (MODE == 0) {
                    *(float2*)&outp[(size_t)m * D_ + n] = o;
                } else {
                    int b = m >> 11, s = m & 2047;
                    int h = n >> 6,  hd = n & 63;
                    *(float2*)&qkv[(((size_t)(b * H_ + h)) * S_ + s) * HD_ + hd] = o;
                }
            }
        }
    }
}

// ---------------------------------------------------------------------------
// Flash attention, tf32 mma (R4-validated version, unchanged).
// CTA: 128 q rows x full head; 8 warps, warp-local softmax.
// ---------------------------------------------------------------------------
#define AP 68
#define ATT_SMEM (384 * AP * 4)

__global__ __launch_bounds__(256, 2)
void attn_mma_kernel()
{
    extern __shared__ float sm[];
    float* Qs = sm;                 // [128][AP]
    float* Ks = sm + 128 * AP;      // [64][AP]
    float* Vt = sm + 192 * AP;      // [64][AP]  (hd x kv)
    float* Ps = sm + 256 * AP;      // [128][AP]

    const int tid = threadIdx.x;
    const int wid = tid >> 5, lid = tid & 31;
    const int g = lid >> 2, tig = lid & 3;
    const int wq = wid * 16;
    const int bh = blockIdx.y;
    const int q0 = blockIdx.x * 128;

    const float* Qb = g_q + (size_t)bh * S_ * HD_;
    const float* Kb = g_k + (size_t)bh * S_ * HD_;
    const float* Vb = g_v + (size_t)bh * S_ * HD_;

    #pragma unroll
    for (int i = 0; i < 8; i++) {
        int idx = tid + i * 256;
        int r = idx >> 4, c4 = (idx & 15) * 4;
        float4 v = *(const float4*)&Qb[(size_t)(q0 + r) * HD_ + c4];
        Qs[r * AP + c4 + 0] = to_tf32(v.x * 0.125f);
        Qs[r * AP + c4 + 1] = to_tf32(v.y * 0.125f);
        Qs[r * AP + c4 + 2] = to_tf32(v.z * 0.125f);
        Qs[r * AP + c4 + 3] = to_tf32(v.w * 0.125f);
    }

    float m_i[2] = {-1e30f, -1e30f}, l_i[2] = {0.f, 0.f};
    float acc[8][4];
    #pragma unroll
    for (int nb = 0; nb < 8; nb++)
        #pragma unroll
        for (int i = 0; i < 4; i++) acc[nb][i] = 0.f;

    for (int t = 0; t < S_; t += 64) {
        __syncthreads();
        #pragma unroll
        for (int i = 0; i < 4; i++) {
            int idx = tid + i * 256;
            int r = idx >> 4, c4 = (idx & 15) * 4;
            float4 kq = *(const float4*)&Kb[(size_t)(t + r) * HD_ + c4];
            Ks[r * AP + c4 + 0] = to_tf32(kq.x);
            Ks[r * AP + c4 + 1] = to_tf32(kq.y);
            Ks[r * AP + c4 + 2] = to_tf32(kq.z);
            Ks[r * AP + c4 + 3] = to_tf32(kq.w);
        }
        #pragma unroll
        for (int i = 0; i < 4; i++) {
            int idx = tid + i * 256;
            int r = (idx >> 1) & 63;
            int c4 = ((idx & 1) | ((idx >> 7) << 1)) * 4;
            float4 vv = *(const float4*)&Vb[(size_t)(t + r) * HD_ + c4];
            Vt[(c4 + 0) * AP + r] = to_tf32(vv.x);
            Vt[(c4 + 1) * AP + r] = to_tf32(vv.y);
            Vt[(c4 + 2) * AP + r] = to_tf32(vv.z);
            Vt[(c4 + 3) * AP + r] = to_tf32(vv.w);
        }
        __syncthreads();

        float s[8][4];
        #pragma unroll
        for (int nb = 0; nb < 8; nb++)
            #pragma unroll
            for (int i = 0; i < 4; i++) s[nb][i] = 0.f;

        #pragma unroll
        for (int kk = 0; kk < 64; kk += 8) {
            uint32_t af[4];
            af[0] = __float_as_uint(Qs[(wq + g    ) * AP + kk + tig]);
            af[1] = __float_as_uint(Qs[(wq + g + 8) * AP + kk + tig]);
            af[2] = __float_as_uint(Qs[(wq + g    ) * AP + kk + tig + 4]);
            af[3] = __float_as_uint(Qs[(wq + g + 8) * AP + kk + tig + 4]);
            #pragma unroll
            for (int nb = 0; nb < 8; nb++) {
                uint32_t bf[2];
                bf[0] = __float_as_uint(Ks[(nb * 8 + g) * AP + kk + tig]);
                bf[1] = __float_as_uint(Ks[(nb * 8 + g) * AP + kk + tig + 4]);
                mma_tf32(s[nb], af, bf);
            }
        }

        float mx[2] = {-1e30f, -1e30f};
        #pragma unroll
        for (int nb = 0; nb < 8; nb++) {
            mx[0] = fmaxf(mx[0], fmaxf(s[nb][0], s[nb][1]));
            mx[1] = fmaxf(mx[1], fmaxf(s[nb][2], s[nb][3]));
        }
        #pragma unroll
        for (int h = 0; h < 2; h++) {
            mx[h] = fmaxf(mx[h], __shfl_xor_sync(0xffffffffu, mx[h], 1));
            mx[h] = fmaxf(mx[h], __shfl_xor_sync(0xffffffffu, mx[h], 2));
        }
        float mnew[2], al[2], rs[2] = {0.f, 0.f};
        #pragma unroll
        for (int h = 0; h < 2; h++) {
            mnew[h] = fmaxf(m_i[h], mx[h]);
            al[h] = __expf(m_i[h] - mnew[h]);
            m_i[h] = mnew[h];
        }
        #pragma unroll
        for (int nb = 0; nb < 8; nb++) {
            s[nb][0] = __expf(s[nb][0] - mnew[0]);
            s[nb][1] = __expf(s[nb][1] - mnew[0]);
            s[nb][2] = __expf(s[nb][2] - mnew[1]);
            s[nb][3] = __expf(s[nb][3] - mnew[1]);
            rs[0] += s[nb][0] + s[nb][1];
            rs[1] += s[nb][2] + s[nb][3];
        }
        #pragma unroll
        for (int h = 0; h < 2; h++) {
            rs[h] += __shfl_xor_sync(0xffffffffu, rs[h], 1);
            rs[h] += __shfl_xor_sync(0xffffffffu, rs[h], 2);
            l_i[h] = l_i[h] * al[h] + rs[h];
        }
        #pragma unroll
        for (int nb = 0; nb < 8; nb++) {
            acc[nb][0] *= al[0]; acc[nb][1] *= al[0];
            acc[nb][2] *= al[1]; acc[nb][3] *= al[1];
        }

        #pragma unroll
        for (int nb = 0; nb < 8; nb++) {
            float2 p0 = make_float2(to_tf32(s[nb][0]), to_tf32(s[nb][1]));
            float2 p1 = make_float2(to_tf32(s[nb][2]), to_tf32(s[nb][3]));
            *(float2*)&Ps[(wq + g    ) * AP + nb * 8 + 2 * tig] = p0;
            *(float2*)&Ps[(wq + g + 8) * AP + nb * 8 + 2 * tig] = p1;
        }
        __syncwarp();

        #pragma unroll
        for (int kk = 0; kk < 64; kk += 8) {
            uint32_t af[4];
            af[0] = __float_as_uint(Ps[(wq + g    ) * AP + kk + tig]);
            af[1] = __float_as_uint(Ps[(wq + g + 8) * AP + kk + tig]);
            af[2] = __float_as_uint(Ps[(wq + g    ) * AP + kk + tig + 4]);
            af[3] = __float_as_uint(Ps[(wq + g + 8) * AP + kk + tig + 4]);
            #pragma unroll
            for (int nb = 0; nb < 8; nb++) {
                uint32_t bf[2];
                bf[0] = __float_as_uint(Vt[(nb * 8 + g) * AP + kk + tig]);
                bf[1] = __float_as_uint(Vt[(nb * 8 + g) * AP + kk + tig + 4]);
                mma_tf32(acc[nb], af, bf);
            }
        }
        __syncwarp();
    }

    const int bb = bh / H_, h = bh % H_;
    const float inv0 = 1.0f / l_i[0], inv1 = 1.0f / l_i[1];
    const int s0 = q0 + wq + g;
    #pragma unroll
    for (int nb = 0; nb < 8; nb++) {
        const int col = h * HD_ + nb * 8 + 2 * tig;
        float2 o0 = make_float2(acc[nb][0] * inv0, acc[nb][1] * inv0);
        float2 o1 = make_float2(acc[nb][2] * inv1, acc[nb][3] * inv1);
        *(float2*)&g_ao[(size_t)(bb * S_ + s0    ) * D_ + col] = o0;
        *(float2*)&g_ao[(size_t)(bb * S_ + s0 + 8) * D_ + col] = o1;
    }
}

// ---------------------------------------------------------------------------
extern "C" void kernel_launch(void* const* d_in, const int* in_sizes, int n_in,
                              void* d_out, int out_size)
{
    const float* x  = (const float*)d_in[0];
    const float* Wq = (const float*)d_in[1];
    const float* bq = (const float*)d_in[2];
    const float* Wk = (const float*)d_in[3];
    const float* bk = (const float*)d_in[4];
    const float* Wv = (const float*)d_in[5];
    const float* bv = (const float*)d_in[6];
    const float* Wo = (const float*)d_in[7];
    const float* bo = (const float*)d_in[8];
    float* out = (float*)d_out;

    static bool attr_done = false;
    if (!attr_done) {
        cudaFuncSetAttribute(attn_mma_kernel,
                             cudaFuncAttributeMaxDynamicSharedMemorySize, ATT_SMEM);
        attr_done = true;
    }

    dim3 gG(D_ / 128, M_ / 128);   // (8, 32)
    gemm_mma_kernel<1><<<gG, 256>>>(x, Wq, bq, nullptr);
    gemm_mma_kernel<2><<<gG, 256>>>(x, Wk, bk, nullptr);
    gemm_mma_kernel<3><<<gG, 256>>>(x, Wv, bv, nullptr);

    dim3 gAttn(S_ / 128, B_ * H_);  // (16, 32)
    attn_mma_kernel<<<gAttn, 256, ATT_SMEM>>>();

    gemm_mma_kernel<0><<<gG, 256>>>(nullptr, Wo, bo, out);
}